// round 1
// baseline (speedup 1.0000x reference)
#include <cuda_runtime.h>
#include <cstdint>

// ---------------------------------------------------------------------------
// Banded causal attention (Longformer sliding window, w=128, window=256, D=64)
// Query i attends keys g in [ks(i), i], ks(i) = max(0, i/128 - 1)*128.
// One CTA = 64 query rows of one head. 256 threads.
// Phase A: S = Q K^T (f32x2 packed FMA), per-warp 8 rows x 256 cols.
// Softmax in registers (warp shuffles). P -> SMEM (aliases K region).
// Phase B: O = P V, split over two 128-key halves + SMEM reduction.
// ---------------------------------------------------------------------------

#define KP 257   // K smem pitch (float2 units), transposed [d2][y]
#define VP 34    // V smem pitch (float2 units), [y][dpair]
#define PP 68    // P smem pitch (float units),  [y][row]

#define SMEM_A 69632                      // max(K 65792, P 69632)
#define SMEM_B 69632                      // V: 256*34*8
#define SMEM_C 16384                      // Q (64*64*4) / O-partials (64*32*8)
#define SMEM_TOTAL (SMEM_A + SMEM_B + SMEM_C)   // 155648 B

static __device__ __forceinline__ void ffma2(unsigned long long& d,
                                             unsigned long long a,
                                             unsigned long long b) {
    asm("fma.rn.f32x2 %0, %1, %2, %0;" : "+l"(d) : "l"(a), "l"(b));
}
static __device__ __forceinline__ unsigned long long pack2(float x, float y) {
    unsigned long long u;
    asm("mov.b64 %0, {%1, %2};" : "=l"(u) : "f"(x), "f"(y));
    return u;
}
static __device__ __forceinline__ float2 unpack2(unsigned long long u) {
    float2 f;
    asm("mov.b64 {%0, %1}, %2;" : "=f"(f.x), "=f"(f.y) : "l"(u));
    return f;
}

// QK inner loop: warp owns rows row0..row0+7, lane owns cols y = lane + 32*j.
// NJ = number of 32-col batches actually needed (causal skip).
template <int NJ>
static __device__ __forceinline__ void qk_loop(const float* __restrict__ Qs,
                                               const unsigned long long* __restrict__ Ku,
                                               int row0, int lane, float s[8][8]) {
    unsigned long long acc[8][NJ];
#pragma unroll
    for (int r = 0; r < 8; ++r) {
#pragma unroll
        for (int j = 0; j < NJ; ++j) acc[r][j] = 0ULL;
    }
#pragma unroll 2
    for (int d2 = 0; d2 < 32; ++d2) {
        unsigned long long q2[8];
#pragma unroll
        for (int r = 0; r < 8; ++r)
            q2[r] = *reinterpret_cast<const unsigned long long*>(Qs + (row0 + r) * 64 + 2 * d2);
#pragma unroll
        for (int j = 0; j < NJ; ++j) {
            unsigned long long k2 = Ku[d2 * KP + lane + 32 * j];
#pragma unroll
            for (int r = 0; r < 8; ++r) ffma2(acc[r][j], q2[r], k2);
        }
    }
#pragma unroll
    for (int r = 0; r < 8; ++r) {
#pragma unroll
        for (int j = 0; j < NJ; ++j) {
            float2 f = unpack2(acc[r][j]);
            s[r][j] = f.x + f.y;
        }
    }
}

__global__ __launch_bounds__(256, 1)
void lf_attn_kernel(const float* __restrict__ Q, const float* __restrict__ K,
                    const float* __restrict__ V, const float* __restrict__ AM,
                    float* __restrict__ O, int S) {
    extern __shared__ char smem_raw[];
    float2* Ks2 = reinterpret_cast<float2*>(smem_raw);              // [32][KP]
    float*  Ps  = reinterpret_cast<float*>(smem_raw);               // [256][PP] (aliases Ks2)
    float2* Vs  = reinterpret_cast<float2*>(smem_raw + SMEM_A);     // [256][VP]
    float*  Qs  = reinterpret_cast<float*>(smem_raw + SMEM_A + SMEM_B);   // [64][64]
    float2* Osc = reinterpret_cast<float2*>(smem_raw + SMEM_A + SMEM_B);  // [64][32] (aliases Qs)

    const int tid   = threadIdx.x;
    const int h     = blockIdx.y;
    const int qrow0 = blockIdx.x * 64;
    const int blk   = qrow0 >> 7;
    const int ks    = (blk > 0 ? blk - 1 : 0) << 7;
    const int nkey  = qrow0 + 64 - ks;   // 64..256

    const float* Qg = Q + ((size_t)h * S + qrow0) * 64;
    const float* Kg = K + ((size_t)h * S + ks) * 64;
    const float* Vg = V + ((size_t)h * S + ks) * 64;

    // ---- stage Q / K(transposed) / V into SMEM ----
#pragma unroll
    for (int rep = 0; rep < 4; ++rep) {
        int idx = rep * 256 + tid;
        int row = idx >> 4, d4 = (idx & 15) << 2;
        float4 val = *reinterpret_cast<const float4*>(Qg + row * 64 + d4);
        *reinterpret_cast<float4*>(Qs + row * 64 + d4) = val;
    }
#pragma unroll
    for (int rep = 0; rep < 16; ++rep) {
        int idx = rep * 256 + tid;
        int y = idx >> 4, d4 = (idx & 15) << 2;
        float4 kv = make_float4(0.f, 0.f, 0.f, 0.f);
        float4 vv = make_float4(0.f, 0.f, 0.f, 0.f);
        if (y < nkey) {
            kv = *reinterpret_cast<const float4*>(Kg + y * 64 + d4);
            vv = *reinterpret_cast<const float4*>(Vg + y * 64 + d4);
        }
        int d2 = d4 >> 1;  // float2 index (even)
        Ks2[(d2    ) * KP + y] = make_float2(kv.x, kv.y);
        Ks2[(d2 + 1) * KP + y] = make_float2(kv.z, kv.w);
        *reinterpret_cast<float4*>(Vs + y * VP + d2) = vv;
    }
    __syncthreads();

    // ---- Phase A: scores ----
    const int lane  = tid & 31;
    const int ry    = tid >> 5;       // warp id -> rows ry*8 .. ry*8+7
    const int row0  = ry * 8;
    const int ymaxw = qrow0 + row0 + 7 - ks;        // max valid col in this warp
    const int nj    = min(8, (ymaxw >> 5) + 1);     // 32-col batches needed

    float s[8][8];
#pragma unroll
    for (int r = 0; r < 8; ++r) {
#pragma unroll
        for (int j = 0; j < 8; ++j) s[r][j] = -1e30f;
    }

    const unsigned long long* Ku = reinterpret_cast<const unsigned long long*>(Ks2);
    switch (nj) {
        case 1: qk_loop<1>(Qs, Ku, row0, lane, s); break;
        case 2: qk_loop<2>(Qs, Ku, row0, lane, s); break;
        case 3: qk_loop<3>(Qs, Ku, row0, lane, s); break;
        case 4: qk_loop<4>(Qs, Ku, row0, lane, s); break;
        case 5: qk_loop<5>(Qs, Ku, row0, lane, s); break;
        case 6: qk_loop<6>(Qs, Ku, row0, lane, s); break;
        case 7: qk_loop<7>(Qs, Ku, row0, lane, s); break;
        default: qk_loop<8>(Qs, Ku, row0, lane, s); break;
    }

    // additive key mask (global index ks + y is always < S by construction)
    float mk[8];
#pragma unroll
    for (int j = 0; j < 8; ++j) mk[j] = AM[ks + lane + 32 * j];

    // ---- softmax (per row, full warp owns the row) ----
    const int ymb = qrow0 + row0 - ks;   // row r limit = ymb + r
#pragma unroll
    for (int r = 0; r < 8; ++r) {
        const int ymax = ymb + r;
        float m = -1e30f;
#pragma unroll
        for (int j = 0; j < 8; ++j) {
            int y = lane + 32 * j;
            float sv = (y <= ymax) ? s[r][j] + mk[j] : -1e30f;
            s[r][j] = sv;
            m = fmaxf(m, sv);
        }
#pragma unroll
        for (int off = 16; off > 0; off >>= 1)
            m = fmaxf(m, __shfl_xor_sync(0xffffffffu, m, off));
        float sum = 0.f;
#pragma unroll
        for (int j = 0; j < 8; ++j) {
            float e = (s[r][j] > -1e29f) ? __expf(s[r][j] - m) : 0.f;
            s[r][j] = e;
            sum += e;
        }
#pragma unroll
        for (int off = 16; off > 0; off >>= 1)
            sum += __shfl_xor_sync(0xffffffffu, sum, off);
        float inv = __frcp_rn(sum);
#pragma unroll
        for (int j = 0; j < 8; ++j) s[r][j] *= inv;
    }

    __syncthreads();   // all K reads complete before P overwrites the region

    // ---- write P to SMEM (transposed [y][row]) ----
#pragma unroll
    for (int j = 0; j < 8; ++j) {
        if (j < nj) {
            int y = lane + 32 * j;
#pragma unroll
            for (int r = 0; r < 8; ++r)
                Ps[y * PP + row0 + r] = s[r][j];
        }
    }
    __syncthreads();

    // ---- Phase B: O = P V, two 128-key halves ----
    const int grp = tid >> 7;           // which key half
    const int t   = tid & 127;
    const int rg  = t >> 3;             // rows rg*4 .. rg*4+3
    const int dpg = t & 7;              // dpairs dpg*4 .. dpg*4+3 (d = dpair*2)
    const int ylim = qrow0 + rg * 4 + 3 - ks;

    unsigned long long o[4][4];
#pragma unroll
    for (int r = 0; r < 4; ++r) {
#pragma unroll
        for (int c = 0; c < 4; ++c) o[r][c] = 0ULL;
    }

    const unsigned long long* Vu = reinterpret_cast<const unsigned long long*>(Vs);
    const int ybeg = grp << 7;
    const int yend = min(ybeg + 128, ylim + 1);
#pragma unroll 2
    for (int y = ybeg; y < yend; ++y) {
        float4 p4 = *reinterpret_cast<const float4*>(Ps + y * PP + rg * 4);
        unsigned long long v0 = Vu[y * VP + dpg * 4 + 0];
        unsigned long long v1 = Vu[y * VP + dpg * 4 + 1];
        unsigned long long v2 = Vu[y * VP + dpg * 4 + 2];
        unsigned long long v3 = Vu[y * VP + dpg * 4 + 3];
        unsigned long long pr;
        pr = pack2(p4.x, p4.x);
        ffma2(o[0][0], pr, v0); ffma2(o[0][1], pr, v1);
        ffma2(o[0][2], pr, v2); ffma2(o[0][3], pr, v3);
        pr = pack2(p4.y, p4.y);
        ffma2(o[1][0], pr, v0); ffma2(o[1][1], pr, v1);
        ffma2(o[1][2], pr, v2); ffma2(o[1][3], pr, v3);
        pr = pack2(p4.z, p4.z);
        ffma2(o[2][0], pr, v0); ffma2(o[2][1], pr, v1);
        ffma2(o[2][2], pr, v2); ffma2(o[2][3], pr, v3);
        pr = pack2(p4.w, p4.w);
        ffma2(o[3][0], pr, v0); ffma2(o[3][1], pr, v1);
        ffma2(o[3][2], pr, v2); ffma2(o[3][3], pr, v3);
    }

    if (grp == 1) {
#pragma unroll
        for (int r = 0; r < 4; ++r) {
#pragma unroll
            for (int c = 0; c < 4; ++c)
                Osc[(rg * 4 + r) * 32 + dpg * 4 + c] = unpack2(o[r][c]);
        }
    }
    __syncthreads();
    if (grp == 0) {
#pragma unroll
        for (int r = 0; r < 4; ++r) {
            int row = rg * 4 + r;
            float2 res[4];
#pragma unroll
            for (int c = 0; c < 4; ++c) {
                float2 a = unpack2(o[r][c]);
                float2 b = Osc[row * 32 + dpg * 4 + c];
                res[c] = make_float2(a.x + b.x, a.y + b.y);
            }
            float* dst = O + ((size_t)h * S + qrow0 + row) * 64 + dpg * 8;
            *reinterpret_cast<float4*>(dst)     = make_float4(res[0].x, res[0].y, res[1].x, res[1].y);
            *reinterpret_cast<float4*>(dst + 4) = make_float4(res[2].x, res[2].y, res[3].x, res[3].y);
        }
    }
}

extern "C" void kernel_launch(void* const* d_in, const int* in_sizes, int n_in,
                              void* d_out, int out_size) {
    const float* Q  = (const float*)d_in[0];
    const float* K  = (const float*)d_in[1];
    const float* V  = (const float*)d_in[2];
    const float* AM = (const float*)d_in[3];
    float* O = (float*)d_out;

    const int S  = in_sizes[3];                 // B=1: mask has S elements
    const int BH = in_sizes[0] / (S * 64);      // B*H heads

    cudaFuncSetAttribute(lf_attn_kernel,
                         cudaFuncAttributeMaxDynamicSharedMemorySize, SMEM_TOTAL);

    dim3 grid(S / 64, BH);
    lf_attn_kernel<<<grid, 256, SMEM_TOTAL>>>(Q, K, V, AM, O, S);
}

// round 3
// speedup vs baseline: 2.4551x; 2.4551x over previous
#include <cuda_runtime.h>
#include <cuda_bf16.h>
#include <cstdint>

// ---------------------------------------------------------------------------
// Banded causal attention (Longformer w=128, window 256, D=64) on mma.sync
// bf16 HMMA with 3-product fp32 emulation. CTA = 128 q-rows, 8 warps.
// ---------------------------------------------------------------------------

#define QP 144u
#define KP 144u
#define VP 144u
#define QHI 0u
#define QLO 18432u
#define KHI 36864u
#define KLO 73728u
#define VHI 110592u
#define VLO 147456u
#define AMS 184320u
#define SMEM_TOTAL 185344

static __device__ __forceinline__ uint32_t smem_u32(const void* p) {
    uint32_t a;
    asm("{ .reg .u64 t; cvta.to.shared.u64 t, %1; cvt.u32.u64 %0, t; }"
        : "=r"(a) : "l"(p));
    return a;
}

// pack two f32 -> bf16x2 (lo = first arg in low half)
static __device__ __forceinline__ uint32_t packb(float lo, float hi) {
    uint32_t r;
    asm("cvt.rn.bf16x2.f32 %0, %1, %2;" : "=r"(r) : "f"(hi), "f"(lo));
    return r;
}

static __device__ __forceinline__ void ldsm4(uint32_t r[4], uint32_t a) {
    asm volatile("ldmatrix.sync.aligned.m8n8.x4.shared.b16 {%0,%1,%2,%3}, [%4];"
                 : "=r"(r[0]), "=r"(r[1]), "=r"(r[2]), "=r"(r[3]) : "r"(a));
}
static __device__ __forceinline__ void ldsm4t(uint32_t r[4], uint32_t a) {
    asm volatile("ldmatrix.sync.aligned.m8n8.x4.trans.shared.b16 {%0,%1,%2,%3}, [%4];"
                 : "=r"(r[0]), "=r"(r[1]), "=r"(r[2]), "=r"(r[3]) : "r"(a));
}
static __device__ __forceinline__ void mma(float d[4], const uint32_t a[4],
                                           uint32_t b0, uint32_t b1) {
    asm volatile(
        "mma.sync.aligned.m16n8k16.row.col.f32.bf16.bf16.f32 "
        "{%0,%1,%2,%3}, {%4,%5,%6,%7}, {%8,%9}, {%0,%1,%2,%3};"
        : "+f"(d[0]), "+f"(d[1]), "+f"(d[2]), "+f"(d[3])
        : "r"(a[0]), "r"(a[1]), "r"(a[2]), "r"(a[3]), "r"(b0), "r"(b1));
}

__global__ __launch_bounds__(256)
void lf_hmma_kernel(const float* __restrict__ Q, const float* __restrict__ K,
                    const float* __restrict__ V, const float* __restrict__ AM,
                    float* __restrict__ O, int S) {
    extern __shared__ char sm[];
    const uint32_t sb = smem_u32(sm);
    const int tid  = threadIdx.x;
    const int w    = tid >> 5;
    const int lane = tid & 31;
    const int g    = lane >> 2;
    const int tg   = lane & 3;
    const int h    = blockIdx.y;
    const int q0   = blockIdx.x << 7;
    const int kb   = q0 - 128;
    const bool blk0 = (q0 == 0);

    const float* Qg = Q + ((size_t)h * S + q0) * 64;
    const float* Kg = K + (size_t)h * S * 64;
    const float* Vg = V + (size_t)h * S * 64;

    // ---- stage Q/K/V (bf16 hi/lo split) + mask into smem ----
#pragma unroll
    for (int it = 0; it < 16; ++it) {
        int idx = it * 256 + tid, row = idx >> 5, c2 = idx & 31;
        float2 q = *reinterpret_cast<const float2*>(Qg + row * 64 + c2 * 2);
        uint32_t hi = packb(q.x, q.y);
        uint32_t lo = packb(q.x - __uint_as_float(hi << 16),
                            q.y - __uint_as_float(hi & 0xffff0000u));
        *reinterpret_cast<uint32_t*>(sm + QHI + row * QP + c2 * 4) = hi;
        *reinterpret_cast<uint32_t*>(sm + QLO + row * QP + c2 * 4) = lo;
    }
#pragma unroll
    for (int it = 0; it < 32; ++it) {
        int idx = it * 256 + tid, y = idx >> 5, c2 = idx & 31;
        float2 kv = make_float2(0.f, 0.f), vv = make_float2(0.f, 0.f);
        if (!blk0 || y >= 128) {
            kv = *reinterpret_cast<const float2*>(Kg + (size_t)(kb + y) * 64 + c2 * 2);
            vv = *reinterpret_cast<const float2*>(Vg + (size_t)(kb + y) * 64 + c2 * 2);
        }
        uint32_t khi = packb(kv.x, kv.y);
        uint32_t klo = packb(kv.x - __uint_as_float(khi << 16),
                             kv.y - __uint_as_float(khi & 0xffff0000u));
        uint32_t vhi = packb(vv.x, vv.y);
        uint32_t vlo = packb(vv.x - __uint_as_float(vhi << 16),
                             vv.y - __uint_as_float(vhi & 0xffff0000u));
        *reinterpret_cast<uint32_t*>(sm + KHI + y * KP + c2 * 4) = khi;
        *reinterpret_cast<uint32_t*>(sm + KLO + y * KP + c2 * 4) = klo;
        *reinterpret_cast<uint32_t*>(sm + VHI + y * VP + c2 * 4) = vhi;
        *reinterpret_cast<uint32_t*>(sm + VLO + y * VP + c2 * 4) = vlo;
    }
    {
        float am = 0.f;
        if (!blk0 || tid >= 128) am = AM[kb + tid];
        reinterpret_cast<float*>(sm + AMS)[tid] = am;
    }
    __syncthreads();

    // ---- A fragments for Q (all 4 k-steps, hi+lo) via ldmatrix ----
    uint32_t aqh[4][4], aql[4][4];
    {
        uint32_t ab = sb + QHI + (uint32_t)(w * 16 + (lane & 15)) * QP +
                      (uint32_t)((lane >> 4) & 1) * 16u;
#pragma unroll
        for (int ks = 0; ks < 4; ++ks) {
            ldsm4(aqh[ks], ab + ks * 32);
            ldsm4(aql[ks], ab + (QLO - QHI) + ks * 32);
        }
    }

    const int ns = blk0 ? 16 : 0;
    const int ne = 18 + 2 * w;   // exclusive n-tile bound (causal)

    union { float s[32][4]; uint32_t u[32][4]; } P;

    const uint32_t kb_h = sb + KHI + (uint32_t)(lane & 7) * KP +
                          (uint32_t)((lane >> 3) & 3) * 16u;
    const uint32_t kb_l = kb_h + (KLO - KHI);

    // ---- Phase A: S = Q K^T (3-product bf16 split) ----
#pragma unroll
    for (int nt = 0; nt < 32; nt += 2) {
        if (nt < ns || nt >= ne) continue;
        float dA0[4] = {0,0,0,0}, dB0[4] = {0,0,0,0};
        float dA1[4] = {0,0,0,0}, dB1[4] = {0,0,0,0};
#pragma unroll
        for (int p = 0; p < 2; ++p) {
            uint32_t bh[4], bl[4], ch[4], cl[4];
            ldsm4(bh, kb_h + (uint32_t)nt * 8u * KP + p * 64);
            ldsm4(bl, kb_l + (uint32_t)nt * 8u * KP + p * 64);
            ldsm4(ch, kb_h + (uint32_t)(nt + 1) * 8u * KP + p * 64);
            ldsm4(cl, kb_l + (uint32_t)(nt + 1) * 8u * KP + p * 64);
            const int k0 = 2 * p, k1 = 2 * p + 1;
            mma(dA0, aqh[k0], bh[0], bh[1]);
            mma(dA1, aqh[k0], ch[0], ch[1]);
            mma(dB0, aqh[k0], bl[0], bl[1]);
            mma(dB1, aqh[k0], cl[0], cl[1]);
            mma(dA0, aqh[k1], bh[2], bh[3]);
            mma(dA1, aqh[k1], ch[2], ch[3]);
            mma(dB0, aqh[k1], bl[2], bl[3]);
            mma(dB1, aqh[k1], cl[2], cl[3]);
            if (p == 0) {
                mma(dA0, aql[k0], bh[0], bh[1]);
                mma(dA1, aql[k0], ch[0], ch[1]);
                mma(dA0, aql[k1], bh[2], bh[3]);
                mma(dA1, aql[k1], ch[2], ch[3]);
            } else {
                mma(dB0, aql[k0], bh[0], bh[1]);
                mma(dB1, aql[k0], ch[0], ch[1]);
                mma(dB0, aql[k1], bh[2], bh[3]);
                mma(dB1, aql[k1], ch[2], ch[3]);
            }
        }
#pragma unroll
        for (int i = 0; i < 4; ++i) {
            P.s[nt][i]     = dA0[i] + dB0[i];
            P.s[nt + 1][i] = dA1[i] + dB1[i];
        }
    }

    // ---- softmax (rows r0 = w*16+g and r0+8; causal + additive mask) ----
    const int r0 = w * 16 + g;
    const int lim0 = 128 + r0, lim1 = lim0 + 8;
    const float* AMsm = reinterpret_cast<const float*>(sm + AMS);

    float m0 = -1e30f, m1 = -1e30f;
#pragma unroll
    for (int nt = 0; nt < 32; ++nt) {
        if (nt < ns || nt >= ne) continue;
        int col0 = nt * 8 + 2 * tg, col1 = col0 + 1;
        float am0 = AMsm[col0], am1 = AMsm[col1];
        float v0 = (col0 <= lim0) ? P.s[nt][0] + am0 : -1e30f;
        float v1 = (col1 <= lim0) ? P.s[nt][1] + am1 : -1e30f;
        float v2 = (col0 <= lim1) ? P.s[nt][2] + am0 : -1e30f;
        float v3 = (col1 <= lim1) ? P.s[nt][3] + am1 : -1e30f;
        P.s[nt][0] = v0; P.s[nt][1] = v1; P.s[nt][2] = v2; P.s[nt][3] = v3;
        m0 = fmaxf(m0, fmaxf(v0, v1));
        m1 = fmaxf(m1, fmaxf(v2, v3));
    }
    m0 = fmaxf(m0, __shfl_xor_sync(0xffffffffu, m0, 1));
    m0 = fmaxf(m0, __shfl_xor_sync(0xffffffffu, m0, 2));
    m1 = fmaxf(m1, __shfl_xor_sync(0xffffffffu, m1, 1));
    m1 = fmaxf(m1, __shfl_xor_sync(0xffffffffu, m1, 2));

    float s0 = 0.f, s1 = 0.f;
#pragma unroll
    for (int nt = 0; nt < 32; ++nt) {
        if (nt < ns || nt >= ne) continue;
        float e0 = __expf(P.s[nt][0] - m0);
        float e1 = __expf(P.s[nt][1] - m0);
        float e2 = __expf(P.s[nt][2] - m1);
        float e3 = __expf(P.s[nt][3] - m1);
        P.s[nt][0] = e0; P.s[nt][1] = e1; P.s[nt][2] = e2; P.s[nt][3] = e3;
        s0 += e0 + e1; s1 += e2 + e3;
    }
    s0 += __shfl_xor_sync(0xffffffffu, s0, 1);
    s0 += __shfl_xor_sync(0xffffffffu, s0, 2);
    s1 += __shfl_xor_sync(0xffffffffu, s1, 1);
    s1 += __shfl_xor_sync(0xffffffffu, s1, 2);
    const float inv0 = __frcp_rn(s0);
    const float inv1 = __frcp_rn(s1);

    // ---- normalize + split P to bf16 hi/lo, packed in place ----
    // layout after: u[nt][0]=hi(row g), u[nt][1]=hi(row g+8), u[nt][2]=lo(g), u[nt][3]=lo(g+8)
#pragma unroll
    for (int nt = 0; nt < 32; ++nt) {
        if (nt < ns || nt >= ne) continue;
        float p0 = P.s[nt][0] * inv0, p1 = P.s[nt][1] * inv0;
        float p2 = P.s[nt][2] * inv1, p3 = P.s[nt][3] * inv1;
        uint32_t h01 = packb(p0, p1);
        uint32_t h23 = packb(p2, p3);
        uint32_t l01 = packb(p0 - __uint_as_float(h01 << 16),
                             p1 - __uint_as_float(h01 & 0xffff0000u));
        uint32_t l23 = packb(p2 - __uint_as_float(h23 << 16),
                             p3 - __uint_as_float(h23 & 0xffff0000u));
        P.u[nt][0] = h01; P.u[nt][1] = h23; P.u[nt][2] = l01; P.u[nt][3] = l23;
    }

    // ---- Phase B: O = P V (3-product split, V via ldmatrix.trans) ----
    float o[8][4];
#pragma unroll
    for (int i = 0; i < 8; ++i) { o[i][0] = o[i][1] = o[i][2] = o[i][3] = 0.f; }

    const uint32_t vb_h = sb + VHI +
        (uint32_t)(((lane >> 3) & 1) * 8 + (lane & 7)) * VP +
        (uint32_t)((lane >> 4) & 1) * 16u;
    const uint32_t vb_l = vb_h + (VLO - VHI);
    const int ktlo = ns >> 1, kthi = ne >> 1;

#pragma unroll
    for (int kt = 0; kt < 16; ++kt) {
        if (kt < ktlo || kt >= kthi) continue;
        uint32_t ah[4] = {P.u[2*kt][0], P.u[2*kt][1], P.u[2*kt+1][0], P.u[2*kt+1][1]};
        uint32_t al[4] = {P.u[2*kt][2], P.u[2*kt][3], P.u[2*kt+1][2], P.u[2*kt+1][3]};
#pragma unroll
        for (int dp = 0; dp < 4; ++dp) {
            uint32_t bh[4], bl[4];
            ldsm4t(bh, vb_h + (uint32_t)kt * 16u * VP + dp * 32);
            ldsm4t(bl, vb_l + (uint32_t)kt * 16u * VP + dp * 32);
            mma(o[2*dp],     ah, bh[0], bh[1]);
            mma(o[2*dp + 1], ah, bh[2], bh[3]);
            mma(o[2*dp],     ah, bl[0], bl[1]);
            mma(o[2*dp + 1], ah, bl[2], bl[3]);
            mma(o[2*dp],     al, bh[0], bh[1]);
            mma(o[2*dp + 1], al, bh[2], bh[3]);
        }
    }

    // ---- store O ----
    float* Ob = O + ((size_t)h * S + q0 + r0) * 64;
#pragma unroll
    for (int dp = 0; dp < 8; ++dp) {
        int d = dp * 8 + 2 * tg;
        *reinterpret_cast<float2*>(Ob + d)           = make_float2(o[dp][0], o[dp][1]);
        *reinterpret_cast<float2*>(Ob + 8 * 64 + d)  = make_float2(o[dp][2], o[dp][3]);
    }
}

extern "C" void kernel_launch(void* const* d_in, const int* in_sizes, int n_in,
                              void* d_out, int out_size) {
    const float* Q  = (const float*)d_in[0];
    const float* K  = (const float*)d_in[1];
    const float* V  = (const float*)d_in[2];
    const float* AM = (const float*)d_in[3];
    float* O = (float*)d_out;

    const int S  = in_sizes[3];
    const int BH = in_sizes[0] / (S * 64);

    cudaFuncSetAttribute(lf_hmma_kernel,
                         cudaFuncAttributeMaxDynamicSharedMemorySize, SMEM_TOTAL);

    dim3 grid(S / 128, BH);
    lf_hmma_kernel<<<grid, 256, SMEM_TOTAL>>>(Q, K, V, AM, O, S);
}